// round 12
// baseline (speedup 1.0000x reference)
#include <cuda_runtime.h>
#include <cuda_bf16.h>
#include <math.h>
#include <stdint.h>

// Problem constants
#define BB 4
#define HH 4
#define LL 2048
#define DD 1024
#define HD 256
#define ROWS (BB*LL)     // 8192
#define BHN  (BB*HH)     // 16

// ---------------- scratch (device globals; no allocations allowed) ----------
__device__ __nv_bfloat16 g_xn_bf [(size_t)ROWS * DD];       // normalized x (bf16)
__device__ __nv_bfloat16 g_wqkv_bf[(size_t)3 * DD * DD];    // qkv_w in bf16
__device__ __nv_bfloat16 g_wout_bf[(size_t)DD * DD];        // out_w in bf16
__device__ float         g_qkv[(size_t)ROWS * 3 * DD];      // qkv projection (fp32)
__device__ float         g_q  [(size_t)BHN * LL * HD];
__device__ float         g_k  [(size_t)BHN * LL * HD];
__device__ float         g_v  [(size_t)BHN * LL * HD];
__device__ __nv_bfloat16 g_ao_bf[(size_t)ROWS * DD];        // attention out (bf16)

// =====================  helpers  ============================================
__device__ __forceinline__ uint32_t smem_u32(const void* p) {
    uint32_t a;
    asm("{ .reg .u64 t; cvta.to.shared.u64 t, %1; cvt.u32.u64 %0, t; }"
        : "=r"(a) : "l"(p));
    return a;
}
__device__ __forceinline__ void ldmx4(uint32_t addr, uint32_t& r0, uint32_t& r1,
                                      uint32_t& r2, uint32_t& r3) {
    asm volatile("ldmatrix.sync.aligned.m8n8.x4.shared.b16 {%0,%1,%2,%3}, [%4];"
                 : "=r"(r0), "=r"(r1), "=r"(r2), "=r"(r3) : "r"(addr));
}
__device__ __forceinline__ void mma16816(float* d, const uint32_t* a,
                                         uint32_t b0, uint32_t b1) {
    asm volatile(
        "mma.sync.aligned.m16n8k16.row.col.f32.bf16.bf16.f32 "
        "{%0,%1,%2,%3}, {%4,%5,%6,%7}, {%8,%9}, {%0,%1,%2,%3};"
        : "+f"(d[0]), "+f"(d[1]), "+f"(d[2]), "+f"(d[3])
        : "r"(a[0]), "r"(a[1]), "r"(a[2]), "r"(a[3]), "r"(b0), "r"(b1));
}
__device__ __forceinline__ void cp16(uint32_t dst, const void* src) {
    asm volatile("cp.async.cg.shared.global [%0], [%1], 16;"
                 :: "r"(dst), "l"(__cvta_generic_to_global(src)));
}
#define CP_COMMIT() asm volatile("cp.async.commit_group;")
#define CP_WAIT(n)  asm volatile("cp.async.wait_group %0;" :: "n"(n))

// ---------------- fp32 -> bf16 convert (weights) ----------------------------
__global__ void f2bf_kernel(const float* __restrict__ src,
                            __nv_bfloat16* __restrict__ dst, int n4)
{
    int i = blockIdx.x * 256 + threadIdx.x;
    if (i < n4) {
        float4 v = ((const float4*)src)[i];
        __nv_bfloat162 h0 = __floats2bfloat162_rn(v.x, v.y);
        __nv_bfloat162 h1 = __floats2bfloat162_rn(v.z, v.w);
        uint2 w;
        w.x = *(uint32_t*)&h0; w.y = *(uint32_t*)&h1;
        ((uint2*)dst)[i] = w;
    }
}

// ---------------- RMSNorm (fp32 in -> bf16 out) ------------------------------
__global__ void rmsnorm_kernel(const float* __restrict__ x,
                               const float* __restrict__ w)
{
    const int row = blockIdx.x;
    const int t = threadIdx.x;
    const float4 v = ((const float4*)(x + (size_t)row * DD))[t];
    float ss = v.x*v.x + v.y*v.y + v.z*v.z + v.w*v.w;
    #pragma unroll
    for (int o = 16; o; o >>= 1) ss += __shfl_xor_sync(0xffffffffu, ss, o);
    __shared__ float swarp[8];
    __shared__ float s_r;
    if ((t & 31) == 0) swarp[t >> 5] = ss;
    __syncthreads();
    if (t < 8) {
        float tot = swarp[t];
        #pragma unroll
        for (int o = 4; o; o >>= 1) tot += __shfl_xor_sync(0xffu, tot, o);
        if (t == 0) s_r = rsqrtf(tot * (1.0f / DD) + 1e-6f);
    }
    __syncthreads();
    const float r = s_r;
    const float4 wv = ((const float4*)w)[t];
    __nv_bfloat162 h0 = __floats2bfloat162_rn(v.x * r * wv.x, v.y * r * wv.y);
    __nv_bfloat162 h1 = __floats2bfloat162_rn(v.z * r * wv.z, v.w * r * wv.w);
    uint2 o2;
    o2.x = *(uint32_t*)&h0; o2.y = *(uint32_t*)&h1;
    ((uint2*)(g_xn_bf + (size_t)row * DD))[t] = o2;
}

// ============ mma.sync bf16 GEMM:  C[M,N] = A[M,K] @ B[N,K]^T  ==============
// CTA tile 128x128, K-chunk 32, 8 warps (warp tile 64x32), cp.async double buf.
// smem rows padded to 40 bf16 (80B) -> conflict-free ldmatrix (gcd(80,128)=16).
#define TPAD 40                      // bf16 per smem row
#define TILE_B (128 * TPAD * 2)      // 10240 bytes per operand tile

template<bool EPI>
__global__ void __launch_bounds__(256) gemm_mma(
    const __nv_bfloat16* __restrict__ A, const __nv_bfloat16* __restrict__ Bm,
    float* __restrict__ C, int N, int K,
    const float* __restrict__ res, const float* __restrict__ rsp)
{
    __shared__ __align__(16) char smem[2 * 2 * TILE_B];   // [buf][A|B]
    const uint32_t s0 = smem_u32(smem);
    const int tid  = threadIdx.x;
    const int lane = tid & 31, wid = tid >> 5;
    const int tM = blockIdx.y * 128, tN = blockIdx.x * 128;
    const int wm = (wid & 1) * 64, wn = (wid >> 1) * 32;

    const __nv_bfloat16* Ag = A  + (size_t)tM * K;
    const __nv_bfloat16* Bg = Bm + (size_t)tN * K;

    float acc[16][4];
    #pragma unroll
    for (int i = 0; i < 16; i++)
        #pragma unroll
        for (int j = 0; j < 4; j++) acc[i][j] = 0.f;

    // chunk loader: 128x32 bf16 per operand, 16B cp.async chunks
    auto load_chunk = [&](int kc, int buf) {
        const uint32_t bufb = s0 + buf * 2 * TILE_B;
        #pragma unroll
        for (int t = 0; t < 2; t++) {
            int idx = tid + t * 256;          // 0..511
            int row = idx >> 2, c = idx & 3;
            uint32_t off = row * (TPAD * 2) + c * 16;
            cp16(bufb + off,          Ag + (size_t)row * K + kc * 32 + c * 8);
            cp16(bufb + TILE_B + off, Bg + (size_t)row * K + kc * 32 + c * 8);
        }
        CP_COMMIT();
    };

    const int NKC = K / 32;
    load_chunk(0, 0);

    const uint32_t rowoff = (lane & 15) * (TPAD * 2);
    const uint32_t colhi  = (lane & 16);   // 0 or 16 bytes

    for (int kc = 0; kc < NKC; kc++) {
        const int cur = kc & 1;
        if (kc + 1 < NKC) { load_chunk(kc + 1, cur ^ 1); CP_WAIT(1); }
        else              { CP_WAIT(0); }
        __syncthreads();

        const uint32_t aT = s0 + cur * 2 * TILE_B + wm * (TPAD * 2);
        const uint32_t bT = s0 + cur * 2 * TILE_B + TILE_B + wn * (TPAD * 2);
        #pragma unroll
        for (int s = 0; s < 2; s++) {
            const uint32_t col = s * 32 + colhi;
            uint32_t br[2][4];
            #pragma unroll
            for (int bj = 0; bj < 2; bj++)
                ldmx4(bT + bj * 16 * (TPAD * 2) + rowoff + col,
                      br[bj][0], br[bj][1], br[bj][2], br[bj][3]);
            #pragma unroll
            for (int mi = 0; mi < 4; mi++) {
                uint32_t a[4];
                ldmx4(aT + mi * 16 * (TPAD * 2) + rowoff + col,
                      a[0], a[1], a[2], a[3]);
                #pragma unroll
                for (int ni = 0; ni < 4; ni++) {
                    const int jj = ni >> 1, p = ni & 1;
                    mma16816(acc[mi * 4 + ni], a, br[jj][p], br[jj][p + 2]);
                }
            }
        }
        __syncthreads();
    }

    // ---- epilogue ----
    const float s_res = EPI ? *rsp : 0.f;
    const int g = lane >> 2, q = lane & 3;
    #pragma unroll
    for (int mi = 0; mi < 4; mi++) {
        const int row0 = tM + wm + mi * 16 + g;
        #pragma unroll
        for (int ni = 0; ni < 4; ni++) {
            const int col = tN + wn + ni * 8 + q * 2;
            const float* ac = acc[mi * 4 + ni];
            #pragma unroll
            for (int h = 0; h < 2; h++) {        // h=0: row0, h=1: row0+8
                const size_t o = (size_t)(row0 + h * 8) * N + col;
                float2 w;
                if (EPI) {
                    float2 r2 = *(const float2*)(res + o);
                    w.x = fmaf(s_res, ac[h * 2 + 0], r2.x);
                    w.y = fmaf(s_res, ac[h * 2 + 1], r2.y);
                } else {
                    w.x = ac[h * 2 + 0];
                    w.y = ac[h * 2 + 1];
                }
                *(float2*)(C + o) = w;
            }
        }
    }
}

// ---------------- RoPE + scatter qkv -> q/k/v in [B,H,L,hd] -----------------
__global__ void rope_scatter_kernel()
{
    const int t  = blockIdx.x * 256 + threadIdx.x;
    const int bl = t / 1536;
    const int r  = t - bl * 1536;
    const int w  = r >> 9;          // 0=q,1=k,2=v
    const int h  = (r >> 7) & 3;
    const int dp = r & 127;
    const float* src = g_qkv + (size_t)bl * 3072 + w * 1024 + h * 256 + dp;
    const float x0 = src[0];
    const float x1 = src[128];
    const int b = bl >> 11;
    const int l = bl & 2047;
    float* base = (w == 0) ? g_q : (w == 1) ? g_k : g_v;
    float* dst = base + ((size_t)(b * HH + h) * LL + l) * HD + dp;
    if (w < 2) {
        const float invf = powf(10000.0f, -(float)dp * (1.0f / 128.0f));
        const float ang  = (float)l * invf;
        const float c = cosf(ang), s = sinf(ang);
        dst[0]   = x0 * c - x1 * s;
        dst[128] = x1 * c + x0 * s;
    } else {
        dst[0]   = x0;
        dst[128] = x1;
    }
}

// ---------------- Flash attention (fp32, online softmax) --------------------
#define FQS 260
#define FPS 68
#define FLASH_SMEM_FLOATS (64*FQS*2 + 64*FPS + 192)
#define FLASH_SMEM_BYTES  (FLASH_SMEM_FLOATS * 4)

__global__ void __launch_bounds__(256) flash_kernel()
{
    extern __shared__ float smf[];
    float* Qs  = smf;
    float* KVs = Qs  + 64 * FQS;
    float* Ps  = KVs + 64 * FQS;
    float* s_m = Ps  + 64 * FPS;
    float* s_l = s_m + 64;
    float* s_a = s_l + 64;

    const int tid = threadIdx.x;
    const int tx  = tid & 15;
    const int ty  = tid >> 4;
    const int bh  = blockIdx.y;
    const int q0  = blockIdx.x * 64;

    const float* Qg = g_q + ((size_t)bh * LL + q0) * HD;
    const float* Kg = g_k + (size_t)bh * LL * HD;
    const float* Vg = g_v + (size_t)bh * LL * HD;

    #pragma unroll
    for (int it = 0; it < 16; it++) {
        int idx = tid + it * 256;
        int rr = idx >> 6, c4 = idx & 63;
        *(float4*)&Qs[rr * FQS + c4 * 4] = ((const float4*)Qg)[idx];
    }
    if (tid < 64) { s_m[tid] = -1e30f; s_l[tid] = 0.f; }

    float o[4][16];
    #pragma unroll
    for (int i = 0; i < 4; i++)
        #pragma unroll
        for (int c = 0; c < 16; c++) o[i][c] = 0.f;

    for (int kt = 0; kt < 32; kt++) {
        const float4* Kt = (const float4*)(Kg + (size_t)kt * 64 * HD);
        #pragma unroll
        for (int it = 0; it < 16; it++) {
            int idx = tid + it * 256;
            int rr = idx >> 6, c4 = idx & 63;
            *(float4*)&KVs[rr * FQS + c4 * 4] = Kt[idx];
        }
        __syncthreads();

        float sacc[4][4];
        #pragma unroll
        for (int i = 0; i < 4; i++)
            #pragma unroll
            for (int j = 0; j < 4; j++) sacc[i][j] = 0.f;
        #pragma unroll 2
        for (int k0 = 0; k0 < HD; k0 += 4) {
            float4 qv[4], kv[4];
            #pragma unroll
            for (int i = 0; i < 4; i++)
                qv[i] = *(const float4*)&Qs[(ty*4 + i) * FQS + k0];
            #pragma unroll
            for (int j = 0; j < 4; j++)
                kv[j] = *(const float4*)&KVs[(tx*4 + j) * FQS + k0];
            #pragma unroll
            for (int i = 0; i < 4; i++)
                #pragma unroll
                for (int j = 0; j < 4; j++) {
                    sacc[i][j] = fmaf(qv[i].x, kv[j].x, sacc[i][j]);
                    sacc[i][j] = fmaf(qv[i].y, kv[j].y, sacc[i][j]);
                    sacc[i][j] = fmaf(qv[i].z, kv[j].z, sacc[i][j]);
                    sacc[i][j] = fmaf(qv[i].w, kv[j].w, sacc[i][j]);
                }
        }
        #pragma unroll
        for (int i = 0; i < 4; i++)
            #pragma unroll
            for (int j = 0; j < 4; j++)
                Ps[(ty*4 + i) * FPS + tx*4 + j] = sacc[i][j] * 0.0625f;
        __syncthreads();

        if (tid < 64) {
            float* pr = Ps + tid * FPS;
            const float mold = s_m[tid];
            float mt = mold;
            #pragma unroll 8
            for (int j = 0; j < 64; j++) mt = fmaxf(mt, pr[j]);
            const float alpha = expf(mold - mt);
            float sum = 0.f;
            #pragma unroll 8
            for (int j = 0; j < 64; j++) {
                float p = expf(pr[j] - mt);
                pr[j] = p;
                sum += p;
            }
            s_l[tid] = s_l[tid] * alpha + sum;
            s_m[tid] = mt;
            s_a[tid] = alpha;
        }
        const float4* Vt = (const float4*)(Vg + (size_t)kt * 64 * HD);
        #pragma unroll
        for (int it = 0; it < 16; it++) {
            int idx = tid + it * 256;
            int rr = idx >> 6, c4 = idx & 63;
            *(float4*)&KVs[rr * FQS + c4 * 4] = Vt[idx];
        }
        __syncthreads();

        #pragma unroll
        for (int i = 0; i < 4; i++) {
            const float a = s_a[ty*4 + i];
            #pragma unroll
            for (int c = 0; c < 16; c++) o[i][c] *= a;
        }
        #pragma unroll 4
        for (int j = 0; j < 64; j++) {
            float pvr[4];
            #pragma unroll
            for (int i = 0; i < 4; i++) pvr[i] = Ps[(ty*4 + i) * FPS + j];
            #pragma unroll
            for (int cc = 0; cc < 4; cc++) {
                float4 v4 = *(const float4*)&KVs[j * FQS + cc*64 + tx*4];
                #pragma unroll
                for (int i = 0; i < 4; i++) {
                    o[i][cc*4+0] = fmaf(pvr[i], v4.x, o[i][cc*4+0]);
                    o[i][cc*4+1] = fmaf(pvr[i], v4.y, o[i][cc*4+1]);
                    o[i][cc*4+2] = fmaf(pvr[i], v4.z, o[i][cc*4+2]);
                    o[i][cc*4+3] = fmaf(pvr[i], v4.w, o[i][cc*4+3]);
                }
            }
        }
        __syncthreads();
    }

    float linv[4];
    #pragma unroll
    for (int i = 0; i < 4; i++) linv[i] = 1.0f / s_l[ty*4 + i];
    const int b = bh >> 2, h = bh & 3;
    #pragma unroll
    for (int i = 0; i < 4; i++) {
        const int l = q0 + ty*4 + i;
        __nv_bfloat16* dst = g_ao_bf + ((size_t)(b * LL + l)) * DD + h * HD;
        #pragma unroll
        for (int cc = 0; cc < 4; cc++) {
            __nv_bfloat162 h0 = __floats2bfloat162_rn(o[i][cc*4+0] * linv[i],
                                                      o[i][cc*4+1] * linv[i]);
            __nv_bfloat162 h1 = __floats2bfloat162_rn(o[i][cc*4+2] * linv[i],
                                                      o[i][cc*4+3] * linv[i]);
            uint2 w;
            w.x = *(uint32_t*)&h0; w.y = *(uint32_t*)&h1;
            *(uint2*)&dst[cc*64 + tx*4] = w;
        }
    }
}

// ---------------- launch -----------------------------------------------------
extern "C" void kernel_launch(void* const* d_in, const int* in_sizes, int n_in,
                              void* d_out, int out_size)
{
    const float* x      = (const float*)d_in[0];
    const float* norm_w = (const float*)d_in[1];
    const float* qkv_w  = (const float*)d_in[2];
    const float* out_w  = (const float*)d_in[3];
    const float* rsp    = (const float*)d_in[4];
    float* out = (float*)d_out;

    __nv_bfloat16 *p_xn, *p_wqkv, *p_wout, *p_ao;
    float *p_qkv;
    cudaGetSymbolAddress((void**)&p_xn,   g_xn_bf);
    cudaGetSymbolAddress((void**)&p_wqkv, g_wqkv_bf);
    cudaGetSymbolAddress((void**)&p_wout, g_wout_bf);
    cudaGetSymbolAddress((void**)&p_qkv,  g_qkv);
    cudaGetSymbolAddress((void**)&p_ao,   g_ao_bf);

    cudaFuncSetAttribute(flash_kernel,
                         cudaFuncAttributeMaxDynamicSharedMemorySize,
                         FLASH_SMEM_BYTES);

    // 0. weights -> bf16
    f2bf_kernel<<<(3 * DD * DD / 4 + 255) / 256, 256>>>(qkv_w, p_wqkv, 3 * DD * DD / 4);
    f2bf_kernel<<<(DD * DD / 4 + 255) / 256, 256>>>(out_w, p_wout, DD * DD / 4);
    // 1. RMSNorm (bf16 out)
    rmsnorm_kernel<<<ROWS, 256>>>(x, norm_w);
    // 2. QKV projection (mma.sync bf16): [8192,3072] = xn @ qkv_w^T
    gemm_mma<false><<<dim3((3 * DD) / 128, ROWS / 128), 256>>>(
        p_xn, p_wqkv, p_qkv, 3 * DD, DD, nullptr, nullptr);
    // 3. RoPE + scatter to [B,H,L,hd]
    rope_scatter_kernel<<<(ROWS * 1536) / 256, 256>>>();
    // 4. attention (fp32)
    flash_kernel<<<dim3(LL / 64, BHN), 256, FLASH_SMEM_BYTES>>>();
    // 5. out projection + residual epilogue (mma.sync bf16) -> d_out
    gemm_mma<true><<<dim3(DD / 128, ROWS / 128), 256>>>(
        p_ao, p_wout, out, DD, DD, x, rsp);
}

// round 13
// speedup vs baseline: 6.0473x; 6.0473x over previous
#include <cuda_runtime.h>
#include <cuda_bf16.h>
#include <math.h>
#include <stdint.h>

// Problem constants
#define BB 4
#define HH 4
#define LL 2048
#define DD 1024
#define HD 256
#define ROWS (BB*LL)     // 8192
#define BHN  (BB*HH)     // 16

// ---------------- scratch (device globals; no allocations allowed) ----------
__device__ __nv_bfloat16 g_xn_bf [(size_t)ROWS * DD];       // normalized x (bf16)
__device__ __nv_bfloat16 g_wqkv_bf[(size_t)3 * DD * DD];    // qkv_w in bf16
__device__ __nv_bfloat16 g_wout_bf[(size_t)DD * DD];        // out_w in bf16
__device__ float         g_qkv[(size_t)ROWS * 3 * DD];      // qkv projection (fp32)
__device__ __nv_bfloat16 g_q  [(size_t)BHN * LL * HD];      // bf16 [BH,L,hd]
__device__ __nv_bfloat16 g_k  [(size_t)BHN * LL * HD];
__device__ __nv_bfloat16 g_v  [(size_t)BHN * LL * HD];
__device__ __nv_bfloat16 g_ao_bf[(size_t)ROWS * DD];        // attention out (bf16)

// =====================  helpers  ============================================
__device__ __forceinline__ uint32_t smem_u32(const void* p) {
    uint32_t a;
    asm("{ .reg .u64 t; cvta.to.shared.u64 t, %1; cvt.u32.u64 %0, t; }"
        : "=r"(a) : "l"(p));
    return a;
}
__device__ __forceinline__ void ldmx4(uint32_t addr, uint32_t& r0, uint32_t& r1,
                                      uint32_t& r2, uint32_t& r3) {
    asm volatile("ldmatrix.sync.aligned.m8n8.x4.shared.b16 {%0,%1,%2,%3}, [%4];"
                 : "=r"(r0), "=r"(r1), "=r"(r2), "=r"(r3) : "r"(addr));
}
__device__ __forceinline__ void ldmx4t(uint32_t addr, uint32_t& r0, uint32_t& r1,
                                       uint32_t& r2, uint32_t& r3) {
    asm volatile("ldmatrix.sync.aligned.m8n8.x4.trans.shared.b16 {%0,%1,%2,%3}, [%4];"
                 : "=r"(r0), "=r"(r1), "=r"(r2), "=r"(r3) : "r"(addr));
}
__device__ __forceinline__ void mma16816(float* d, const uint32_t* a,
                                         uint32_t b0, uint32_t b1) {
    asm volatile(
        "mma.sync.aligned.m16n8k16.row.col.f32.bf16.bf16.f32 "
        "{%0,%1,%2,%3}, {%4,%5,%6,%7}, {%8,%9}, {%0,%1,%2,%3};"
        : "+f"(d[0]), "+f"(d[1]), "+f"(d[2]), "+f"(d[3])
        : "r"(a[0]), "r"(a[1]), "r"(a[2]), "r"(a[3]), "r"(b0), "r"(b1));
}
__device__ __forceinline__ void cp16(uint32_t dst, const void* src) {
    asm volatile("cp.async.cg.shared.global [%0], [%1], 16;"
                 :: "r"(dst), "l"(__cvta_generic_to_global(src)));
}
#define CP_COMMIT() asm volatile("cp.async.commit_group;")
#define CP_WAIT(n)  asm volatile("cp.async.wait_group %0;" :: "n"(n))

// ---------------- fp32 -> bf16 convert (weights) ----------------------------
__global__ void f2bf_kernel(const float* __restrict__ src,
                            __nv_bfloat16* __restrict__ dst, int n4)
{
    int i = blockIdx.x * 256 + threadIdx.x;
    if (i < n4) {
        float4 v = ((const float4*)src)[i];
        __nv_bfloat162 h0 = __floats2bfloat162_rn(v.x, v.y);
        __nv_bfloat162 h1 = __floats2bfloat162_rn(v.z, v.w);
        uint2 w;
        w.x = *(uint32_t*)&h0; w.y = *(uint32_t*)&h1;
        ((uint2*)dst)[i] = w;
    }
}

// ---------------- RMSNorm (fp32 in -> bf16 out) ------------------------------
__global__ void rmsnorm_kernel(const float* __restrict__ x,
                               const float* __restrict__ w)
{
    const int row = blockIdx.x;
    const int t = threadIdx.x;
    const float4 v = ((const float4*)(x + (size_t)row * DD))[t];
    float ss = v.x*v.x + v.y*v.y + v.z*v.z + v.w*v.w;
    #pragma unroll
    for (int o = 16; o; o >>= 1) ss += __shfl_xor_sync(0xffffffffu, ss, o);
    __shared__ float swarp[8];
    __shared__ float s_r;
    if ((t & 31) == 0) swarp[t >> 5] = ss;
    __syncthreads();
    if (t < 8) {
        float tot = swarp[t];
        #pragma unroll
        for (int o = 4; o; o >>= 1) tot += __shfl_xor_sync(0xffu, tot, o);
        if (t == 0) s_r = rsqrtf(tot * (1.0f / DD) + 1e-6f);
    }
    __syncthreads();
    const float r = s_r;
    const float4 wv = ((const float4*)w)[t];
    __nv_bfloat162 h0 = __floats2bfloat162_rn(v.x * r * wv.x, v.y * r * wv.y);
    __nv_bfloat162 h1 = __floats2bfloat162_rn(v.z * r * wv.z, v.w * r * wv.w);
    uint2 o2;
    o2.x = *(uint32_t*)&h0; o2.y = *(uint32_t*)&h1;
    ((uint2*)(g_xn_bf + (size_t)row * DD))[t] = o2;
}

// ============ mma.sync bf16 GEMM:  C[M,N] = A[M,K] @ B[N,K]^T  ==============
#define TPAD 40                      // bf16 per smem row
#define TILE_B (128 * TPAD * 2)      // 10240 bytes per operand tile

template<bool EPI>
__global__ void __launch_bounds__(256) gemm_mma(
    const __nv_bfloat16* __restrict__ A, const __nv_bfloat16* __restrict__ Bm,
    float* __restrict__ C, int N, int K,
    const float* __restrict__ res, const float* __restrict__ rsp)
{
    __shared__ __align__(16) char smem[2 * 2 * TILE_B];   // [buf][A|B]
    const uint32_t s0 = smem_u32(smem);
    const int tid  = threadIdx.x;
    const int lane = tid & 31, wid = tid >> 5;
    const int tM = blockIdx.y * 128, tN = blockIdx.x * 128;
    const int wm = (wid & 1) * 64, wn = (wid >> 1) * 32;

    const __nv_bfloat16* Ag = A  + (size_t)tM * K;
    const __nv_bfloat16* Bg = Bm + (size_t)tN * K;

    float acc[16][4];
    #pragma unroll
    for (int i = 0; i < 16; i++)
        #pragma unroll
        for (int j = 0; j < 4; j++) acc[i][j] = 0.f;

    auto load_chunk = [&](int kc, int buf) {
        const uint32_t bufb = s0 + buf * 2 * TILE_B;
        #pragma unroll
        for (int t = 0; t < 2; t++) {
            int idx = tid + t * 256;          // 0..511
            int row = idx >> 2, c = idx & 3;
            uint32_t off = row * (TPAD * 2) + c * 16;
            cp16(bufb + off,          Ag + (size_t)row * K + kc * 32 + c * 8);
            cp16(bufb + TILE_B + off, Bg + (size_t)row * K + kc * 32 + c * 8);
        }
        CP_COMMIT();
    };

    const int NKC = K / 32;
    load_chunk(0, 0);

    const uint32_t rowoff = (lane & 15) * (TPAD * 2);
    const uint32_t colhi  = (lane & 16);

    for (int kc = 0; kc < NKC; kc++) {
        const int cur = kc & 1;
        if (kc + 1 < NKC) { load_chunk(kc + 1, cur ^ 1); CP_WAIT(1); }
        else              { CP_WAIT(0); }
        __syncthreads();

        const uint32_t aT = s0 + cur * 2 * TILE_B + wm * (TPAD * 2);
        const uint32_t bT = s0 + cur * 2 * TILE_B + TILE_B + wn * (TPAD * 2);
        #pragma unroll
        for (int s = 0; s < 2; s++) {
            const uint32_t col = s * 32 + colhi;
            uint32_t br[2][4];
            #pragma unroll
            for (int bj = 0; bj < 2; bj++)
                ldmx4(bT + bj * 16 * (TPAD * 2) + rowoff + col,
                      br[bj][0], br[bj][1], br[bj][2], br[bj][3]);
            #pragma unroll
            for (int mi = 0; mi < 4; mi++) {
                uint32_t a[4];
                ldmx4(aT + mi * 16 * (TPAD * 2) + rowoff + col,
                      a[0], a[1], a[2], a[3]);
                #pragma unroll
                for (int ni = 0; ni < 4; ni++) {
                    const int jj = ni >> 1, p = ni & 1;
                    mma16816(acc[mi * 4 + ni], a, br[jj][p], br[jj][p + 2]);
                }
            }
        }
        __syncthreads();
    }

    const float s_res = EPI ? *rsp : 0.f;
    const int g = lane >> 2, q = lane & 3;
    #pragma unroll
    for (int mi = 0; mi < 4; mi++) {
        const int row0 = tM + wm + mi * 16 + g;
        #pragma unroll
        for (int ni = 0; ni < 4; ni++) {
            const int col = tN + wn + ni * 8 + q * 2;
            const float* ac = acc[mi * 4 + ni];
            #pragma unroll
            for (int h = 0; h < 2; h++) {
                const size_t o = (size_t)(row0 + h * 8) * N + col;
                float2 w;
                if (EPI) {
                    float2 r2 = *(const float2*)(res + o);
                    w.x = fmaf(s_res, ac[h * 2 + 0], r2.x);
                    w.y = fmaf(s_res, ac[h * 2 + 1], r2.y);
                } else {
                    w.x = ac[h * 2 + 0];
                    w.y = ac[h * 2 + 1];
                }
                *(float2*)(C + o) = w;
            }
        }
    }
}

// ---------------- RoPE + scatter qkv -> q/k/v (bf16) in [B,H,L,hd] ----------
__global__ void rope_scatter_kernel()
{
    const int t  = blockIdx.x * 256 + threadIdx.x;
    const int bl = t / 1536;
    const int r  = t - bl * 1536;
    const int w  = r >> 9;          // 0=q,1=k,2=v
    const int h  = (r >> 7) & 3;
    const int dp = r & 127;
    const float* src = g_qkv + (size_t)bl * 3072 + w * 1024 + h * 256 + dp;
    const float x0 = src[0];
    const float x1 = src[128];
    const int b = bl >> 11;
    const int l = bl & 2047;
    __nv_bfloat16* base = (w == 0) ? g_q : (w == 1) ? g_k : g_v;
    __nv_bfloat16* dst = base + ((size_t)(b * HH + h) * LL + l) * HD + dp;
    if (w < 2) {
        const float invf = powf(10000.0f, -(float)dp * (1.0f / 128.0f));
        const float ang  = (float)l * invf;
        const float c = cosf(ang), s = sinf(ang);
        dst[0]   = __float2bfloat16(x0 * c - x1 * s);
        dst[128] = __float2bfloat16(x1 * c + x0 * s);
    } else {
        dst[0]   = __float2bfloat16(x0);
        dst[128] = __float2bfloat16(x1);
    }
}

// ---------------- Flash attention (bf16 mma.sync, online softmax) -----------
// CTA: 128 q-rows x full K loop (64-key tiles). 8 warps / 256 threads.
// smem: Q[128x264] K[64x264] V[64x264] bf16; S[128x68] fp32; P[128x72] bf16.
#define KSTB 528              // 264 bf16 row stride (bytes)
#define SST  68               // fp32 S stride (floats)
#define PSTB 144              // 72 bf16 P stride (bytes)
#define OFF_K 67584
#define OFF_V 101376
#define OFF_P 135168
#define OFF_S 153600
#define OFF_ST 188416
#define FLASH_SMEM 189952

__global__ void __launch_bounds__(256, 1) flash_mma()
{
    extern __shared__ char fsm[];
    const uint32_t sb = smem_u32(fsm);
    const uint32_t sQ = sb, sK = sb + OFF_K, sV = sb + OFF_V;
    const uint32_t sP = sb + OFF_P;
    float* Ss   = (float*)(fsm + OFF_S);
    float* s_m  = (float*)(fsm + OFF_ST);
    float* s_l  = s_m + 128;
    float* s_al = s_l + 128;

    const int tid = threadIdx.x;
    const int lane = tid & 31, wid = tid >> 5;
    const int g = lane >> 2, qd = lane & 3;
    const int m0 = (wid & 3) * 32;
    const int nS = (wid >> 2) * 32;      // S-stage warp col base (64 keys)
    const int nO = (wid >> 2) * 128;     // PV-stage warp col base (256 hd)
    const int bh = blockIdx.y;
    const int q0 = blockIdx.x * 128;

    const __nv_bfloat16* Qg = g_q + ((size_t)bh * LL + q0) * HD;
    const __nv_bfloat16* Kg = g_k + (size_t)bh * LL * HD;
    const __nv_bfloat16* Vg = g_v + (size_t)bh * LL * HD;

    // load Q tile (128 x 256 bf16)
    #pragma unroll
    for (int it = 0; it < 16; it++) {
        int idx = tid + it * 256;            // 4096 16B chunks
        int row = idx >> 5, c = idx & 31;
        uint4 v = ((const uint4*)(Qg + (size_t)row * HD))[c];
        *(uint4*)(fsm + row * KSTB + c * 16) = v;
    }
    if (tid < 128) { s_m[tid] = -1e30f; s_l[tid] = 0.f; }

    float accO[2][16][4];
    #pragma unroll
    for (int mi = 0; mi < 2; mi++)
        #pragma unroll
        for (int nj = 0; nj < 16; nj++)
            #pragma unroll
            for (int k = 0; k < 4; k++) accO[mi][nj][k] = 0.f;

    const uint32_t lrow = (lane & 15);
    const uint32_t lhi  = (lane & 16);

    for (int kt = 0; kt < 32; kt++) {
        // async K then V tile loads (2048 16B chunks each / 256 threads)
        const __nv_bfloat16* Kt = Kg + (size_t)kt * 64 * HD;
        const __nv_bfloat16* Vt = Vg + (size_t)kt * 64 * HD;
        #pragma unroll
        for (int t = 0; t < 8; t++) {
            int idx = tid + t * 256;
            int row = idx >> 5, c = idx & 31;
            cp16(sK + row * KSTB + c * 16, Kt + (size_t)row * HD + c * 8);
        }
        CP_COMMIT();
        #pragma unroll
        for (int t = 0; t < 8; t++) {
            int idx = tid + t * 256;
            int row = idx >> 5, c = idx & 31;
            cp16(sV + row * KSTB + c * 16, Vt + (size_t)row * HD + c * 8);
        }
        CP_COMMIT();
        CP_WAIT(1);                  // K ready (V may still be in flight)
        __syncthreads();

        // ---- S = Q K^T  (warp tile 32x32, k = 256) ----
        float acc[2][4][4];
        #pragma unroll
        for (int mi = 0; mi < 2; mi++)
            #pragma unroll
            for (int nj = 0; nj < 4; nj++)
                #pragma unroll
                for (int k = 0; k < 4; k++) acc[mi][nj][k] = 0.f;
        #pragma unroll
        for (int ks = 0; ks < 16; ks++) {
            const uint32_t colb = ks * 32 + lhi;
            uint32_t br0[4], br1[4];
            ldmx4(sK + (nS + lrow) * KSTB + colb, br0[0], br0[1], br0[2], br0[3]);
            ldmx4(sK + (nS + 16 + lrow) * KSTB + colb, br1[0], br1[1], br1[2], br1[3]);
            #pragma unroll
            for (int mi = 0; mi < 2; mi++) {
                uint32_t a[4];
                ldmx4(sQ + (m0 + mi * 16 + lrow) * KSTB + colb, a[0], a[1], a[2], a[3]);
                mma16816(acc[mi][0], a, br0[0], br0[2]);
                mma16816(acc[mi][1], a, br0[1], br0[3]);
                mma16816(acc[mi][2], a, br1[0], br1[2]);
                mma16816(acc[mi][3], a, br1[1], br1[3]);
            }
        }
        // write S * scale to smem (fp32)
        #pragma unroll
        for (int mi = 0; mi < 2; mi++) {
            const int row = m0 + mi * 16 + g;
            #pragma unroll
            for (int nj = 0; nj < 4; nj++) {
                const int col = nS + nj * 8 + qd * 2;
                float2 w0, w1;
                w0.x = acc[mi][nj][0] * 0.0625f; w0.y = acc[mi][nj][1] * 0.0625f;
                w1.x = acc[mi][nj][2] * 0.0625f; w1.y = acc[mi][nj][3] * 0.0625f;
                *(float2*)&Ss[row * SST + col]       = w0;
                *(float2*)&Ss[(row + 8) * SST + col] = w1;
            }
        }
        CP_WAIT(0);                  // V ready
        __syncthreads();

        // ---- online softmax: 2 threads per row ----
        {
            const int row = tid >> 1, half = tid & 1;
            const float* sr = Ss + row * SST + half * 32;
            const float mold = s_m[row];
            float mx = mold;
            #pragma unroll 8
            for (int j = 0; j < 32; j++) mx = fmaxf(mx, sr[j]);
            mx = fmaxf(mx, __shfl_xor_sync(0xffffffffu, mx, 1));
            const float alpha = __expf(mold - mx);
            float sum = 0.f;
            uint32_t pbase = sP + row * PSTB + half * 64;
            #pragma unroll 8
            for (int j = 0; j < 32; j += 2) {
                float2 s2 = *(const float2*)(sr + j);
                float p0 = __expf(s2.x - mx);
                float p1 = __expf(s2.y - mx);
                sum += p0 + p1;
                __nv_bfloat162 ph = __floats2bfloat162_rn(p0, p1);
                asm volatile("st.shared.b32 [%0], %1;"
                             :: "r"(pbase + j * 2), "r"(*(uint32_t*)&ph));
            }
            sum += __shfl_xor_sync(0xffffffffu, sum, 1);
            if (!half) {
                s_m[row] = mx;
                s_l[row] = s_l[row] * alpha + sum;
                s_al[row] = alpha;
            }
        }
        __syncthreads();

        // ---- O = O*alpha + P V  (warp tile 32x128, k = 64) ----
        #pragma unroll
        for (int mi = 0; mi < 2; mi++) {
            const float a1 = s_al[m0 + mi * 16 + g];
            const float a2 = s_al[m0 + mi * 16 + g + 8];
            #pragma unroll
            for (int nj = 0; nj < 16; nj++) {
                accO[mi][nj][0] *= a1; accO[mi][nj][1] *= a1;
                accO[mi][nj][2] *= a2; accO[mi][nj][3] *= a2;
            }
        }
        #pragma unroll
        for (int ks = 0; ks < 4; ks++) {
            const uint32_t colb = ks * 32 + lhi;
            const uint32_t vrow = ks * 16 + lrow;
            uint32_t vb[8][4];
            #pragma unroll
            for (int np = 0; np < 8; np++)
                ldmx4t(sV + vrow * KSTB + (nO + np * 16) * 2 + lhi,
                       vb[np][0], vb[np][1], vb[np][2], vb[np][3]);
            #pragma unroll
            for (int mi = 0; mi < 2; mi++) {
                uint32_t a[4];
                ldmx4(sP + (m0 + mi * 16 + lrow) * PSTB + colb, a[0], a[1], a[2], a[3]);
                #pragma unroll
                for (int np = 0; np < 8; np++) {
                    mma16816(accO[mi][np * 2 + 0], a, vb[np][0], vb[np][1]);
                    mma16816(accO[mi][np * 2 + 1], a, vb[np][2], vb[np][3]);
                }
            }
        }
        __syncthreads();
    }

    // ---- epilogue: O /= l, write bf16 to g_ao_bf [B,L,H*hd] ----
    const int b = bh >> 2, h = bh & 3;
    #pragma unroll
    for (int mi = 0; mi < 2; mi++) {
        const int r = m0 + mi * 16 + g;
        const float li1 = 1.0f / s_l[r];
        const float li2 = 1.0f / s_l[r + 8];
        __nv_bfloat16* d1 = g_ao_bf + ((size_t)(b * LL + q0 + r) * DD + h * HD);
        __nv_bfloat16* d2 = d1 + 8 * DD;
        #pragma unroll
        for (int nj = 0; nj < 16; nj++) {
            const int col = nO + nj * 8 + qd * 2;
            __nv_bfloat162 h1 = __floats2bfloat162_rn(accO[mi][nj][0] * li1,
                                                      accO[mi][nj][1] * li1);
            __nv_bfloat162 h2 = __floats2bfloat162_rn(accO[mi][nj][2] * li2,
                                                      accO[mi][nj][3] * li2);
            *(uint32_t*)(d1 + col) = *(uint32_t*)&h1;
            *(uint32_t*)(d2 + col) = *(uint32_t*)&h2;
        }
    }
}

// ---------------- launch -----------------------------------------------------
extern "C" void kernel_launch(void* const* d_in, const int* in_sizes, int n_in,
                              void* d_out, int out_size)
{
    const float* x      = (const float*)d_in[0];
    const float* norm_w = (const float*)d_in[1];
    const float* qkv_w  = (const float*)d_in[2];
    const float* out_w  = (const float*)d_in[3];
    const float* rsp    = (const float*)d_in[4];
    float* out = (float*)d_out;

    __nv_bfloat16 *p_xn, *p_wqkv, *p_wout, *p_ao;
    float *p_qkv;
    cudaGetSymbolAddress((void**)&p_xn,   g_xn_bf);
    cudaGetSymbolAddress((void**)&p_wqkv, g_wqkv_bf);
    cudaGetSymbolAddress((void**)&p_wout, g_wout_bf);
    cudaGetSymbolAddress((void**)&p_qkv,  g_qkv);
    cudaGetSymbolAddress((void**)&p_ao,   g_ao_bf);

    cudaFuncSetAttribute(flash_mma,
                         cudaFuncAttributeMaxDynamicSharedMemorySize,
                         FLASH_SMEM);

    // 0. weights -> bf16
    f2bf_kernel<<<(3 * DD * DD / 4 + 255) / 256, 256>>>(qkv_w, p_wqkv, 3 * DD * DD / 4);
    f2bf_kernel<<<(DD * DD / 4 + 255) / 256, 256>>>(out_w, p_wout, DD * DD / 4);
    // 1. RMSNorm (bf16 out)
    rmsnorm_kernel<<<ROWS, 256>>>(x, norm_w);
    // 2. QKV projection (mma.sync bf16): [8192,3072] = xn @ qkv_w^T
    gemm_mma<false><<<dim3((3 * DD) / 128, ROWS / 128), 256>>>(
        p_xn, p_wqkv, p_qkv, 3 * DD, DD, nullptr, nullptr);
    // 3. RoPE + scatter to bf16 [B,H,L,hd]
    rope_scatter_kernel<<<(ROWS * 1536) / 256, 256>>>();
    // 4. attention (bf16 mma.sync flash)
    flash_mma<<<dim3(LL / 128, BHN), 256, FLASH_SMEM>>>();
    // 5. out projection + residual epilogue (mma.sync bf16) -> d_out
    gemm_mma<true><<<dim3(DD / 128, ROWS / 128), 256>>>(
        p_ao, p_wout, out, DD, DD, x, rsp);
}

// round 14
// speedup vs baseline: 7.0100x; 1.1592x over previous
#include <cuda_runtime.h>
#include <cuda_bf16.h>
#include <math.h>
#include <stdint.h>

// Problem constants
#define BB 4
#define HH 4
#define LL 2048
#define DD 1024
#define HD 256
#define ROWS (BB*LL)     // 8192
#define BHN  (BB*HH)     // 16

// ---------------- scratch (device globals; no allocations allowed) ----------
__device__ __nv_bfloat16 g_xn_bf [(size_t)ROWS * DD];       // normalized x (bf16)
__device__ __nv_bfloat16 g_wqkv_bf[(size_t)3 * DD * DD];    // qkv_w in bf16
__device__ __nv_bfloat16 g_wout_bf[(size_t)DD * DD];        // out_w in bf16
__device__ __nv_bfloat16 g_qkv_bf[(size_t)ROWS * 3 * DD];   // qkv projection (bf16)
__device__ __nv_bfloat16 g_q  [(size_t)BHN * LL * HD];      // bf16 [BH,L,hd]
__device__ __nv_bfloat16 g_k  [(size_t)BHN * LL * HD];
__device__ __nv_bfloat16 g_v  [(size_t)BHN * LL * HD];
__device__ __nv_bfloat16 g_ao_bf[(size_t)ROWS * DD];        // attention out (bf16)

// =====================  helpers  ============================================
__device__ __forceinline__ uint32_t smem_u32(const void* p) {
    uint32_t a;
    asm("{ .reg .u64 t; cvta.to.shared.u64 t, %1; cvt.u32.u64 %0, t; }"
        : "=r"(a) : "l"(p));
    return a;
}
__device__ __forceinline__ void ldmx4(uint32_t addr, uint32_t& r0, uint32_t& r1,
                                      uint32_t& r2, uint32_t& r3) {
    asm volatile("ldmatrix.sync.aligned.m8n8.x4.shared.b16 {%0,%1,%2,%3}, [%4];"
                 : "=r"(r0), "=r"(r1), "=r"(r2), "=r"(r3) : "r"(addr));
}
__device__ __forceinline__ void ldmx4t(uint32_t addr, uint32_t& r0, uint32_t& r1,
                                       uint32_t& r2, uint32_t& r3) {
    asm volatile("ldmatrix.sync.aligned.m8n8.x4.trans.shared.b16 {%0,%1,%2,%3}, [%4];"
                 : "=r"(r0), "=r"(r1), "=r"(r2), "=r"(r3) : "r"(addr));
}
__device__ __forceinline__ void mma16816(float* d, const uint32_t* a,
                                         uint32_t b0, uint32_t b1) {
    asm volatile(
        "mma.sync.aligned.m16n8k16.row.col.f32.bf16.bf16.f32 "
        "{%0,%1,%2,%3}, {%4,%5,%6,%7}, {%8,%9}, {%0,%1,%2,%3};"
        : "+f"(d[0]), "+f"(d[1]), "+f"(d[2]), "+f"(d[3])
        : "r"(a[0]), "r"(a[1]), "r"(a[2]), "r"(a[3]), "r"(b0), "r"(b1));
}
__device__ __forceinline__ void cp16(uint32_t dst, const void* src) {
    asm volatile("cp.async.cg.shared.global [%0], [%1], 16;"
                 :: "r"(dst), "l"(__cvta_generic_to_global(src)));
}
#define CP_COMMIT() asm volatile("cp.async.commit_group;")
#define CP_WAIT(n)  asm volatile("cp.async.wait_group %0;" :: "n"(n))
__device__ __forceinline__ float ex2f(float x) {
    float y;
    asm("ex2.approx.f32 %0, %1;" : "=f"(y) : "f"(x));
    return y;
}

// ---------------- fp32 -> bf16 convert (weights) ----------------------------
__global__ void f2bf_kernel(const float* __restrict__ src,
                            __nv_bfloat16* __restrict__ dst, int n4)
{
    int i = blockIdx.x * 256 + threadIdx.x;
    if (i < n4) {
        float4 v = ((const float4*)src)[i];
        __nv_bfloat162 h0 = __floats2bfloat162_rn(v.x, v.y);
        __nv_bfloat162 h1 = __floats2bfloat162_rn(v.z, v.w);
        uint2 w;
        w.x = *(uint32_t*)&h0; w.y = *(uint32_t*)&h1;
        ((uint2*)dst)[i] = w;
    }
}

// ---------------- RMSNorm (fp32 in -> bf16 out) ------------------------------
__global__ void rmsnorm_kernel(const float* __restrict__ x,
                               const float* __restrict__ w)
{
    const int row = blockIdx.x;
    const int t = threadIdx.x;
    const float4 v = ((const float4*)(x + (size_t)row * DD))[t];
    float ss = v.x*v.x + v.y*v.y + v.z*v.z + v.w*v.w;
    #pragma unroll
    for (int o = 16; o; o >>= 1) ss += __shfl_xor_sync(0xffffffffu, ss, o);
    __shared__ float swarp[8];
    __shared__ float s_r;
    if ((t & 31) == 0) swarp[t >> 5] = ss;
    __syncthreads();
    if (t < 8) {
        float tot = swarp[t];
        #pragma unroll
        for (int o = 4; o; o >>= 1) tot += __shfl_xor_sync(0xffu, tot, o);
        if (t == 0) s_r = rsqrtf(tot * (1.0f / DD) + 1e-6f);
    }
    __syncthreads();
    const float r = s_r;
    const float4 wv = ((const float4*)w)[t];
    __nv_bfloat162 h0 = __floats2bfloat162_rn(v.x * r * wv.x, v.y * r * wv.y);
    __nv_bfloat162 h1 = __floats2bfloat162_rn(v.z * r * wv.z, v.w * r * wv.w);
    uint2 o2;
    o2.x = *(uint32_t*)&h0; o2.y = *(uint32_t*)&h1;
    ((uint2*)(g_xn_bf + (size_t)row * DD))[t] = o2;
}

// ============ mma.sync bf16 GEMM:  C[M,N] = A[M,K] @ B[N,K]^T  ==============
#define TPAD 40                      // bf16 per smem row
#define TILE_B (128 * TPAD * 2)      // 10240 bytes per operand tile

// OBF: write bf16 output.  EPI: C = res + (*rsp)*acc (fp32 out).
template<bool EPI, bool OBF>
__global__ void __launch_bounds__(256) gemm_mma(
    const __nv_bfloat16* __restrict__ A, const __nv_bfloat16* __restrict__ Bm,
    void* __restrict__ Cv, int N, int K,
    const float* __restrict__ res, const float* __restrict__ rsp)
{
    __shared__ __align__(16) char smem[2 * 2 * TILE_B];   // [buf][A|B]
    const uint32_t s0 = smem_u32(smem);
    const int tid  = threadIdx.x;
    const int lane = tid & 31, wid = tid >> 5;
    const int tM = blockIdx.y * 128, tN = blockIdx.x * 128;
    const int wm = (wid & 1) * 64, wn = (wid >> 1) * 32;

    const __nv_bfloat16* Ag = A  + (size_t)tM * K;
    const __nv_bfloat16* Bg = Bm + (size_t)tN * K;

    float acc[16][4];
    #pragma unroll
    for (int i = 0; i < 16; i++)
        #pragma unroll
        for (int j = 0; j < 4; j++) acc[i][j] = 0.f;

    auto load_chunk = [&](int kc, int buf) {
        const uint32_t bufb = s0 + buf * 2 * TILE_B;
        #pragma unroll
        for (int t = 0; t < 2; t++) {
            int idx = tid + t * 256;          // 0..511
            int row = idx >> 2, c = idx & 3;
            uint32_t off = row * (TPAD * 2) + c * 16;
            cp16(bufb + off,          Ag + (size_t)row * K + kc * 32 + c * 8);
            cp16(bufb + TILE_B + off, Bg + (size_t)row * K + kc * 32 + c * 8);
        }
        CP_COMMIT();
    };

    const int NKC = K / 32;
    load_chunk(0, 0);

    const uint32_t rowoff = (lane & 15) * (TPAD * 2);
    const uint32_t colhi  = (lane & 16);

    for (int kc = 0; kc < NKC; kc++) {
        const int cur = kc & 1;
        if (kc + 1 < NKC) { load_chunk(kc + 1, cur ^ 1); CP_WAIT(1); }
        else              { CP_WAIT(0); }
        __syncthreads();

        const uint32_t aT = s0 + cur * 2 * TILE_B + wm * (TPAD * 2);
        const uint32_t bT = s0 + cur * 2 * TILE_B + TILE_B + wn * (TPAD * 2);
        #pragma unroll
        for (int s = 0; s < 2; s++) {
            const uint32_t col = s * 32 + colhi;
            uint32_t br[2][4];
            #pragma unroll
            for (int bj = 0; bj < 2; bj++)
                ldmx4(bT + bj * 16 * (TPAD * 2) + rowoff + col,
                      br[bj][0], br[bj][1], br[bj][2], br[bj][3]);
            #pragma unroll
            for (int mi = 0; mi < 4; mi++) {
                uint32_t a[4];
                ldmx4(aT + mi * 16 * (TPAD * 2) + rowoff + col,
                      a[0], a[1], a[2], a[3]);
                #pragma unroll
                for (int ni = 0; ni < 4; ni++) {
                    const int jj = ni >> 1, p = ni & 1;
                    mma16816(acc[mi * 4 + ni], a, br[jj][p], br[jj][p + 2]);
                }
            }
        }
        __syncthreads();
    }

    const float s_res = EPI ? *rsp : 0.f;
    const int g = lane >> 2, q = lane & 3;
    #pragma unroll
    for (int mi = 0; mi < 4; mi++) {
        const int row0 = tM + wm + mi * 16 + g;
        #pragma unroll
        for (int ni = 0; ni < 4; ni++) {
            const int col = tN + wn + ni * 8 + q * 2;
            const float* ac = acc[mi * 4 + ni];
            #pragma unroll
            for (int h = 0; h < 2; h++) {
                const size_t o = (size_t)(row0 + h * 8) * N + col;
                if (OBF) {
                    __nv_bfloat162 hp = __floats2bfloat162_rn(ac[h * 2 + 0],
                                                              ac[h * 2 + 1]);
                    *(uint32_t*)((__nv_bfloat16*)Cv + o) = *(uint32_t*)&hp;
                } else {
                    float2 w;
                    if (EPI) {
                        float2 r2 = *(const float2*)(res + o);
                        w.x = fmaf(s_res, ac[h * 2 + 0], r2.x);
                        w.y = fmaf(s_res, ac[h * 2 + 1], r2.y);
                    } else {
                        w.x = ac[h * 2 + 0];
                        w.y = ac[h * 2 + 1];
                    }
                    *(float2*)((float*)Cv + o) = w;
                }
            }
        }
    }
}

// ---------------- RoPE + scatter qkv(bf16) -> q/k/v (bf16) [B,H,L,hd] -------
__global__ void rope_scatter_kernel()
{
    const int t  = blockIdx.x * 256 + threadIdx.x;
    const int bl = t / 1536;
    const int r  = t - bl * 1536;
    const int w  = r >> 9;          // 0=q,1=k,2=v
    const int h  = (r >> 7) & 3;
    const int dp = r & 127;
    const __nv_bfloat16* src = g_qkv_bf + (size_t)bl * 3072 + w * 1024 + h * 256 + dp;
    const float x0 = __bfloat162float(src[0]);
    const float x1 = __bfloat162float(src[128]);
    const int b = bl >> 11;
    const int l = bl & 2047;
    __nv_bfloat16* base = (w == 0) ? g_q : (w == 1) ? g_k : g_v;
    __nv_bfloat16* dst = base + ((size_t)(b * HH + h) * LL + l) * HD + dp;
    if (w < 2) {
        const float invf = powf(10000.0f, -(float)dp * (1.0f / 128.0f));
        const float ang  = (float)l * invf;
        const float c = cosf(ang), s = sinf(ang);
        dst[0]   = __float2bfloat16(x0 * c - x1 * s);
        dst[128] = __float2bfloat16(x1 * c + x0 * s);
    } else {
        dst[0]   = __float2bfloat16(x0);
        dst[128] = __float2bfloat16(x1);
    }
}

// ---------------- Flash attention v2 (register-resident softmax) ------------
// CTA = 128 q-rows; 8 warps; each warp owns 16 q-rows x ALL 64 keys x 256 hd.
// S accumulator stays in registers; exp'd fragment re-packed as PV A-operand.
// K/V double-buffered in smem via cp.async (2 groups/tile).
#define FKSTB 528               // 264 bf16 row stride (bytes)
#define FK_OFF 67584            // Q tile bytes (128 x 264 bf16)
#define FV_OFF 135168
#define FKV_BUF 33792           // one K or V buffer (64 x 264 bf16)
#define FLASH_SMEM 202752

__global__ void __launch_bounds__(256, 1) flash_mma()
{
    extern __shared__ char fsm[];
    const uint32_t sQ = smem_u32(fsm);
    const uint32_t sK = sQ + FK_OFF, sV = sQ + FV_OFF;

    const int tid = threadIdx.x;
    const int lane = tid & 31, wid = tid >> 5;
    const int g = lane >> 2, qd = lane & 3;
    const int m0w = wid * 16;
    const int bh = blockIdx.y;
    const int q0 = blockIdx.x * 128;

    const __nv_bfloat16* Qg = g_q + ((size_t)bh * LL + q0) * HD;
    const __nv_bfloat16* Kg = g_k + (size_t)bh * LL * HD;
    const __nv_bfloat16* Vg = g_v + (size_t)bh * LL * HD;

    // load Q tile (128 x 256 bf16)
    #pragma unroll
    for (int it = 0; it < 16; it++) {
        int idx = tid + it * 256;            // 4096 16B chunks
        int row = idx >> 5, c = idx & 31;
        uint4 v = ((const uint4*)(Qg + (size_t)row * HD))[c];
        *(uint4*)(fsm + row * FKSTB + c * 16) = v;
    }

    auto load_kv = [&](int kt, int buf) {
        const __nv_bfloat16* Kt = Kg + (size_t)kt * 64 * HD;
        const __nv_bfloat16* Vt = Vg + (size_t)kt * 64 * HD;
        const uint32_t kb = sK + buf * FKV_BUF;
        const uint32_t vb = sV + buf * FKV_BUF;
        #pragma unroll
        for (int t = 0; t < 8; t++) {
            int idx = tid + t * 256;
            int row = idx >> 5, c = idx & 31;
            cp16(kb + row * FKSTB + c * 16, Kt + (size_t)row * HD + c * 8);
        }
        CP_COMMIT();
        #pragma unroll
        for (int t = 0; t < 8; t++) {
            int idx = tid + t * 256;
            int row = idx >> 5, c = idx & 31;
            cp16(vb + row * FKSTB + c * 16, Vt + (size_t)row * HD + c * 8);
        }
        CP_COMMIT();
    };

    float accO[32][4];
    #pragma unroll
    for (int nj = 0; nj < 32; nj++)
        #pragma unroll
        for (int k = 0; k < 4; k++) accO[nj][k] = 0.f;
    float rm0 = -1e30f, rm1 = -1e30f, rl0 = 0.f, rl1 = 0.f;

    const uint32_t lrow = (lane & 15), lhi = (lane & 16);
    const float SC = 0.0625f * 1.44269504f;   // 1/sqrt(256) * log2(e)

    load_kv(0, 0);

    for (int kt = 0; kt < 32; kt++) {
        const int cur = kt & 1;
        if (kt < 31) { load_kv(kt + 1, cur ^ 1); CP_WAIT(2); }
        else         { CP_WAIT(0); }
        __syncthreads();
        const uint32_t sKb = sK + cur * FKV_BUF;
        const uint32_t sVb = sV + cur * FKV_BUF;

        // ---- S = Q K^T  (warp tile 16 x 64, k = 256) ----
        float accS[8][4];
        #pragma unroll
        for (int nj = 0; nj < 8; nj++)
            #pragma unroll
            for (int k = 0; k < 4; k++) accS[nj][k] = 0.f;
        #pragma unroll
        for (int ks = 0; ks < 16; ks++) {
            const uint32_t colb = ks * 32 + lhi;
            uint32_t a[4];
            ldmx4(sQ + (m0w + lrow) * FKSTB + colb, a[0], a[1], a[2], a[3]);
            #pragma unroll
            for (int kb = 0; kb < 4; kb++) {
                uint32_t br[4];
                ldmx4(sKb + (kb * 16 + lrow) * FKSTB + colb,
                      br[0], br[1], br[2], br[3]);
                mma16816(accS[kb * 2 + 0], a, br[0], br[2]);
                mma16816(accS[kb * 2 + 1], a, br[1], br[3]);
            }
        }

        // ---- register softmax (rows g and g+8 of this warp's 16) ----
        #pragma unroll
        for (int nj = 0; nj < 8; nj++)
            #pragma unroll
            for (int k = 0; k < 4; k++) accS[nj][k] *= SC;
        float mx0 = rm0, mx1 = rm1;
        #pragma unroll
        for (int nj = 0; nj < 8; nj++) {
            mx0 = fmaxf(mx0, fmaxf(accS[nj][0], accS[nj][1]));
            mx1 = fmaxf(mx1, fmaxf(accS[nj][2], accS[nj][3]));
        }
        mx0 = fmaxf(mx0, __shfl_xor_sync(0xffffffffu, mx0, 1));
        mx0 = fmaxf(mx0, __shfl_xor_sync(0xffffffffu, mx0, 2));
        mx1 = fmaxf(mx1, __shfl_xor_sync(0xffffffffu, mx1, 1));
        mx1 = fmaxf(mx1, __shfl_xor_sync(0xffffffffu, mx1, 2));
        const float al0 = ex2f(rm0 - mx0);
        const float al1 = ex2f(rm1 - mx1);
        rm0 = mx0; rm1 = mx1;

        float sum0 = 0.f, sum1 = 0.f;
        uint32_t pa[4][4];
        #pragma unroll
        for (int nj = 0; nj < 8; nj++) {
            float p0 = ex2f(accS[nj][0] - mx0);
            float p1 = ex2f(accS[nj][1] - mx0);
            float p2 = ex2f(accS[nj][2] - mx1);
            float p3 = ex2f(accS[nj][3] - mx1);
            sum0 += p0 + p1;
            sum1 += p2 + p3;
            __nv_bfloat162 h01 = __floats2bfloat162_rn(p0, p1);
            __nv_bfloat162 h23 = __floats2bfloat162_rn(p2, p3);
            const int kk = nj >> 1, hf = nj & 1;
            pa[kk][hf * 2 + 0] = *(uint32_t*)&h01;
            pa[kk][hf * 2 + 1] = *(uint32_t*)&h23;
        }
        sum0 += __shfl_xor_sync(0xffffffffu, sum0, 1);
        sum0 += __shfl_xor_sync(0xffffffffu, sum0, 2);
        sum1 += __shfl_xor_sync(0xffffffffu, sum1, 1);
        sum1 += __shfl_xor_sync(0xffffffffu, sum1, 2);
        rl0 = rl0 * al0 + sum0;
        rl1 = rl1 * al1 + sum1;

        // ---- O = O*alpha + P V  (warp tile 16 x 256, k = 64) ----
        #pragma unroll
        for (int nj = 0; nj < 32; nj++) {
            accO[nj][0] *= al0; accO[nj][1] *= al0;
            accO[nj][2] *= al1; accO[nj][3] *= al1;
        }
        #pragma unroll
        for (int ks = 0; ks < 4; ks++) {
            const uint32_t vrow = ks * 16 + lrow;
            #pragma unroll
            for (int np = 0; np < 16; np++) {
                uint32_t vb[4];
                ldmx4t(sVb + vrow * FKSTB + np * 32 + lhi,
                       vb[0], vb[1], vb[2], vb[3]);
                mma16816(accO[np * 2 + 0], pa[ks], vb[0], vb[1]);
                mma16816(accO[np * 2 + 1], pa[ks], vb[2], vb[3]);
            }
        }
        __syncthreads();
    }

    // ---- epilogue: O /= l, write bf16 to g_ao_bf [B,L,H*hd] ----
    const int b = bh >> 2, h = bh & 3;
    const int r0 = q0 + m0w + g;
    const float li0 = 1.0f / rl0;
    const float li1 = 1.0f / rl1;
    __nv_bfloat16* d1 = g_ao_bf + ((size_t)(b * LL + r0) * DD + h * HD);
    __nv_bfloat16* d2 = d1 + 8 * DD;
    #pragma unroll
    for (int nj = 0; nj < 32; nj++) {
        const int col = nj * 8 + qd * 2;
        __nv_bfloat162 h1 = __floats2bfloat162_rn(accO[nj][0] * li0,
                                                  accO[nj][1] * li0);
        __nv_bfloat162 h2 = __floats2bfloat162_rn(accO[nj][2] * li1,
                                                  accO[nj][3] * li1);
        *(uint32_t*)(d1 + col) = *(uint32_t*)&h1;
        *(uint32_t*)(d2 + col) = *(uint32_t*)&h2;
    }
}

// ---------------- launch -----------------------------------------------------
extern "C" void kernel_launch(void* const* d_in, const int* in_sizes, int n_in,
                              void* d_out, int out_size)
{
    const float* x      = (const float*)d_in[0];
    const float* norm_w = (const float*)d_in[1];
    const float* qkv_w  = (const float*)d_in[2];
    const float* out_w  = (const float*)d_in[3];
    const float* rsp    = (const float*)d_in[4];
    float* out = (float*)d_out;

    __nv_bfloat16 *p_xn, *p_wqkv, *p_wout, *p_ao, *p_qkv;
    cudaGetSymbolAddress((void**)&p_xn,   g_xn_bf);
    cudaGetSymbolAddress((void**)&p_wqkv, g_wqkv_bf);
    cudaGetSymbolAddress((void**)&p_wout, g_wout_bf);
    cudaGetSymbolAddress((void**)&p_qkv,  g_qkv_bf);
    cudaGetSymbolAddress((void**)&p_ao,   g_ao_bf);

    cudaFuncSetAttribute(flash_mma,
                         cudaFuncAttributeMaxDynamicSharedMemorySize,
                         FLASH_SMEM);

    // 0. weights -> bf16
    f2bf_kernel<<<(3 * DD * DD / 4 + 255) / 256, 256>>>(qkv_w, p_wqkv, 3 * DD * DD / 4);
    f2bf_kernel<<<(DD * DD / 4 + 255) / 256, 256>>>(out_w, p_wout, DD * DD / 4);
    // 1. RMSNorm (bf16 out)
    rmsnorm_kernel<<<ROWS, 256>>>(x, norm_w);
    // 2. QKV projection (mma.sync bf16, bf16 out): [8192,3072] = xn @ qkv_w^T
    gemm_mma<false, true><<<dim3((3 * DD) / 128, ROWS / 128), 256>>>(
        p_xn, p_wqkv, p_qkv, 3 * DD, DD, nullptr, nullptr);
    // 3. RoPE + scatter to bf16 [B,H,L,hd]
    rope_scatter_kernel<<<(ROWS * 1536) / 256, 256>>>();
    // 4. attention (register-resident FA2, bf16 mma.sync)
    flash_mma<<<dim3(LL / 128, BHN), 256, FLASH_SMEM>>>();
    // 5. out projection + residual epilogue -> d_out (fp32)
    gemm_mma<true, false><<<dim3(DD / 128, ROWS / 128), 256>>>(
        p_ao, p_wout, out, DD, DD, x, rsp);
}

// round 15
// speedup vs baseline: 7.4978x; 1.0696x over previous
#include <cuda_runtime.h>
#include <cuda_bf16.h>
#include <math.h>
#include <stdint.h>

// Problem constants
#define BB 4
#define HH 4
#define LL 2048
#define DD 1024
#define HD 256
#define ROWS (BB*LL)     // 8192
#define BHN  (BB*HH)     // 16

// ---------------- scratch (device globals; no allocations allowed) ----------
__device__ __nv_bfloat16 g_xn_bf [(size_t)ROWS * DD];       // normalized x (bf16)
__device__ __nv_bfloat16 g_wqkv_bf[(size_t)3 * DD * DD];    // qkv_w in bf16
__device__ __nv_bfloat16 g_wout_bf[(size_t)DD * DD];        // out_w in bf16
__device__ __nv_bfloat16 g_qkv_bf[(size_t)ROWS * 3 * DD];   // qkv projection (bf16)
__device__ __nv_bfloat16 g_q  [(size_t)BHN * LL * HD];      // bf16 [BH,L,hd]
__device__ __nv_bfloat16 g_k  [(size_t)BHN * LL * HD];
__device__ __nv_bfloat16 g_v  [(size_t)BHN * LL * HD];
__device__ __nv_bfloat16 g_ao_bf[(size_t)ROWS * DD];        // attention out (bf16)

// =====================  helpers  ============================================
__device__ __forceinline__ uint32_t smem_u32(const void* p) {
    uint32_t a;
    asm("{ .reg .u64 t; cvta.to.shared.u64 t, %1; cvt.u32.u64 %0, t; }"
        : "=r"(a) : "l"(p));
    return a;
}
__device__ __forceinline__ void ldmx4(uint32_t addr, uint32_t& r0, uint32_t& r1,
                                      uint32_t& r2, uint32_t& r3) {
    asm volatile("ldmatrix.sync.aligned.m8n8.x4.shared.b16 {%0,%1,%2,%3}, [%4];"
                 : "=r"(r0), "=r"(r1), "=r"(r2), "=r"(r3) : "r"(addr));
}
__device__ __forceinline__ void ldmx4t(uint32_t addr, uint32_t& r0, uint32_t& r1,
                                       uint32_t& r2, uint32_t& r3) {
    asm volatile("ldmatrix.sync.aligned.m8n8.x4.trans.shared.b16 {%0,%1,%2,%3}, [%4];"
                 : "=r"(r0), "=r"(r1), "=r"(r2), "=r"(r3) : "r"(addr));
}
__device__ __forceinline__ void mma16816(float* d, const uint32_t* a,
                                         uint32_t b0, uint32_t b1) {
    asm volatile(
        "mma.sync.aligned.m16n8k16.row.col.f32.bf16.bf16.f32 "
        "{%0,%1,%2,%3}, {%4,%5,%6,%7}, {%8,%9}, {%0,%1,%2,%3};"
        : "+f"(d[0]), "+f"(d[1]), "+f"(d[2]), "+f"(d[3])
        : "r"(a[0]), "r"(a[1]), "r"(a[2]), "r"(a[3]), "r"(b0), "r"(b1));
}
__device__ __forceinline__ void cp16(uint32_t dst, const void* src) {
    asm volatile("cp.async.cg.shared.global [%0], [%1], 16;"
                 :: "r"(dst), "l"(__cvta_generic_to_global(src)));
}
#define CP_COMMIT() asm volatile("cp.async.commit_group;")
#define CP_WAIT(n)  asm volatile("cp.async.wait_group %0;" :: "n"(n))
__device__ __forceinline__ float ex2f(float x) {
    float y;
    asm("ex2.approx.f32 %0, %1;" : "=f"(y) : "f"(x));
    return y;
}

// ---------------- fp32 -> bf16 convert (weights) ----------------------------
__global__ void f2bf_kernel(const float* __restrict__ src,
                            __nv_bfloat16* __restrict__ dst, int n4)
{
    int i = blockIdx.x * 256 + threadIdx.x;
    if (i < n4) {
        float4 v = ((const float4*)src)[i];
        __nv_bfloat162 h0 = __floats2bfloat162_rn(v.x, v.y);
        __nv_bfloat162 h1 = __floats2bfloat162_rn(v.z, v.w);
        uint2 w;
        w.x = *(uint32_t*)&h0; w.y = *(uint32_t*)&h1;
        ((uint2*)dst)[i] = w;
    }
}

// ---------------- RMSNorm (fp32 in -> bf16 out) ------------------------------
__global__ void rmsnorm_kernel(const float* __restrict__ x,
                               const float* __restrict__ w)
{
    const int row = blockIdx.x;
    const int t = threadIdx.x;
    const float4 v = ((const float4*)(x + (size_t)row * DD))[t];
    float ss = v.x*v.x + v.y*v.y + v.z*v.z + v.w*v.w;
    #pragma unroll
    for (int o = 16; o; o >>= 1) ss += __shfl_xor_sync(0xffffffffu, ss, o);
    __shared__ float swarp[8];
    __shared__ float s_r;
    if ((t & 31) == 0) swarp[t >> 5] = ss;
    __syncthreads();
    if (t < 8) {
        float tot = swarp[t];
        #pragma unroll
        for (int o = 4; o; o >>= 1) tot += __shfl_xor_sync(0xffu, tot, o);
        if (t == 0) s_r = rsqrtf(tot * (1.0f / DD) + 1e-6f);
    }
    __syncthreads();
    const float r = s_r;
    const float4 wv = ((const float4*)w)[t];
    __nv_bfloat162 h0 = __floats2bfloat162_rn(v.x * r * wv.x, v.y * r * wv.y);
    __nv_bfloat162 h1 = __floats2bfloat162_rn(v.z * r * wv.z, v.w * r * wv.w);
    uint2 o2;
    o2.x = *(uint32_t*)&h0; o2.y = *(uint32_t*)&h1;
    ((uint2*)(g_xn_bf + (size_t)row * DD))[t] = o2;
}

// ============ mma.sync bf16 GEMM:  C[M,N] = A[M,K] @ B[N,K]^T  ==============
// CTA tile 128x128, 4 warps (warp tile 64x64), K-chunk 32, 3-stage cp.async.
// smem rows padded to 80B -> conflict-free ldmatrix.
#define GPAD 80                        // bytes per 32-bf16 smem row
#define GTILE (128 * GPAD)             // 10240 bytes per operand per stage
#define GSTAGE (2 * GTILE)             // A+B per stage
#define GSMEM (3 * GSTAGE)             // 61440 bytes

// OBF: write bf16 output.  EPI: C = res + (*rsp)*acc (fp32 out).
template<bool EPI, bool OBF>
__global__ void __launch_bounds__(128) gemm_mma(
    const __nv_bfloat16* __restrict__ A, const __nv_bfloat16* __restrict__ Bm,
    void* __restrict__ Cv, int N, int K,
    const float* __restrict__ res, const float* __restrict__ rsp)
{
    extern __shared__ char gsm[];
    const uint32_t s0 = smem_u32(gsm);
    const int tid  = threadIdx.x;
    const int lane = tid & 31, wid = tid >> 5;
    const int tM = blockIdx.y * 128, tN = blockIdx.x * 128;
    const int wm = (wid & 1) * 64, wn = (wid >> 1) * 64;

    const __nv_bfloat16* Ag = A  + (size_t)tM * K;
    const __nv_bfloat16* Bg = Bm + (size_t)tN * K;

    float acc[32][4];
    #pragma unroll
    for (int i = 0; i < 32; i++)
        #pragma unroll
        for (int j = 0; j < 4; j++) acc[i][j] = 0.f;

    // stage loader: 128x32 bf16 per operand (4 cp16 / thread / operand)
    auto load_stage = [&](int kc, int st) {
        const uint32_t base = s0 + st * GSTAGE;
        #pragma unroll
        for (int t = 0; t < 4; t++) {
            int idx = tid + t * 128;          // 0..511
            int row = idx >> 2, c = idx & 3;
            uint32_t off = row * GPAD + c * 16;
            cp16(base + off,         Ag + (size_t)row * K + kc * 32 + c * 8);
            cp16(base + GTILE + off, Bg + (size_t)row * K + kc * 32 + c * 8);
        }
        CP_COMMIT();
    };

    const int NKC = K / 32;
    load_stage(0, 0);
    load_stage(1, 1);

    const uint32_t rowoff = (lane & 15) * GPAD;
    const uint32_t colhi  = (lane & 16);

    int st = 0;
    for (int kc = 0; kc < NKC; kc++) {
        CP_WAIT(1);
        __syncthreads();

        const uint32_t aT = s0 + st * GSTAGE + wm * GPAD;
        const uint32_t bT = s0 + st * GSTAGE + GTILE + wn * GPAD;
        #pragma unroll
        for (int s = 0; s < 2; s++) {
            const uint32_t col = s * 32 + colhi;
            uint32_t a[4][4], b[4][4];
            #pragma unroll
            for (int mi = 0; mi < 4; mi++)
                ldmx4(aT + mi * 16 * GPAD + rowoff + col,
                      a[mi][0], a[mi][1], a[mi][2], a[mi][3]);
            #pragma unroll
            for (int ni = 0; ni < 4; ni++)
                ldmx4(bT + ni * 16 * GPAD + rowoff + col,
                      b[ni][0], b[ni][1], b[ni][2], b[ni][3]);
            #pragma unroll
            for (int mi = 0; mi < 4; mi++)
                #pragma unroll
                for (int ni = 0; ni < 4; ni++) {
                    mma16816(acc[mi * 8 + ni * 2 + 0], a[mi], b[ni][0], b[ni][2]);
                    mma16816(acc[mi * 8 + ni * 2 + 1], a[mi], b[ni][1], b[ni][3]);
                }
        }

        if (kc + 2 < NKC)
            load_stage(kc + 2, (st + 2 >= 3) ? st - 1 : st + 2);
        st = (st + 1 == 3) ? 0 : st + 1;
    }

    // ---- epilogue ----
    const float s_res = EPI ? *rsp : 0.f;
    const int g = lane >> 2, q = lane & 3;
    #pragma unroll
    for (int mi = 0; mi < 4; mi++) {
        const int row0 = tM + wm + mi * 16 + g;
        #pragma unroll
        for (int nj = 0; nj < 8; nj++) {
            const int col = tN + wn + nj * 8 + q * 2;
            const float* ac = acc[mi * 8 + nj];
            #pragma unroll
            for (int h = 0; h < 2; h++) {
                const size_t o = (size_t)(row0 + h * 8) * N + col;
                if (OBF) {
                    __nv_bfloat162 hp = __floats2bfloat162_rn(ac[h * 2 + 0],
                                                              ac[h * 2 + 1]);
                    *(uint32_t*)((__nv_bfloat16*)Cv + o) = *(uint32_t*)&hp;
                } else {
                    float2 w;
                    if (EPI) {
                        float2 r2 = *(const float2*)(res + o);
                        w.x = fmaf(s_res, ac[h * 2 + 0], r2.x);
                        w.y = fmaf(s_res, ac[h * 2 + 1], r2.y);
                    } else {
                        w.x = ac[h * 2 + 0];
                        w.y = ac[h * 2 + 1];
                    }
                    *(float2*)((float*)Cv + o) = w;
                }
            }
        }
    }
}

// ---------------- RoPE + scatter qkv(bf16) -> q/k/v (bf16) [B,H,L,hd] -------
__global__ void rope_scatter_kernel()
{
    const int t  = blockIdx.x * 256 + threadIdx.x;
    const int bl = t / 1536;
    const int r  = t - bl * 1536;
    const int w  = r >> 9;          // 0=q,1=k,2=v
    const int h  = (r >> 7) & 3;
    const int dp = r & 127;
    const __nv_bfloat16* src = g_qkv_bf + (size_t)bl * 3072 + w * 1024 + h * 256 + dp;
    const float x0 = __bfloat162float(src[0]);
    const float x1 = __bfloat162float(src[128]);
    const int b = bl >> 11;
    const int l = bl & 2047;
    __nv_bfloat16* base = (w == 0) ? g_q : (w == 1) ? g_k : g_v;
    __nv_bfloat16* dst = base + ((size_t)(b * HH + h) * LL + l) * HD + dp;
    if (w < 2) {
        // 10000^(-dp/128) = 2^(-dp * log2(10000)/128)
        const float invf = exp2f((float)dp * (-13.287712379549449f / 128.0f));
        const float ang  = (float)l * invf;
        float s, c;
        sincosf(ang, &s, &c);
        dst[0]   = __float2bfloat16(x0 * c - x1 * s);
        dst[128] = __float2bfloat16(x1 * c + x0 * s);
    } else {
        dst[0]   = __float2bfloat16(x0);
        dst[128] = __float2bfloat16(x1);
    }
}

// ---------------- Flash attention v2 (register-resident softmax) ------------
// CTA = 128 q-rows; 8 warps; each warp owns 16 q-rows x ALL 64 keys x 256 hd.
#define FKSTB 528               // 264 bf16 row stride (bytes)
#define FK_OFF 67584            // Q tile bytes (128 x 264 bf16)
#define FV_OFF 135168
#define FKV_BUF 33792           // one K or V buffer (64 x 264 bf16)
#define FLASH_SMEM 202752

__global__ void __launch_bounds__(256, 1) flash_mma()
{
    extern __shared__ char fsm[];
    const uint32_t sQ = smem_u32(fsm);
    const uint32_t sK = sQ + FK_OFF, sV = sQ + FV_OFF;

    const int tid = threadIdx.x;
    const int lane = tid & 31, wid = tid >> 5;
    const int g = lane >> 2, qd = lane & 3;
    const int m0w = wid * 16;
    const int bh = blockIdx.y;
    const int q0 = blockIdx.x * 128;

    const __nv_bfloat16* Qg = g_q + ((size_t)bh * LL + q0) * HD;
    const __nv_bfloat16* Kg = g_k + (size_t)bh * LL * HD;
    const __nv_bfloat16* Vg = g_v + (size_t)bh * LL * HD;

    // load Q tile (128 x 256 bf16)
    #pragma unroll
    for (int it = 0; it < 16; it++) {
        int idx = tid + it * 256;            // 4096 16B chunks
        int row = idx >> 5, c = idx & 31;
        uint4 v = ((const uint4*)(Qg + (size_t)row * HD))[c];
        *(uint4*)(fsm + row * FKSTB + c * 16) = v;
    }

    auto load_kv = [&](int kt, int buf) {
        const __nv_bfloat16* Kt = Kg + (size_t)kt * 64 * HD;
        const __nv_bfloat16* Vt = Vg + (size_t)kt * 64 * HD;
        const uint32_t kb = sK + buf * FKV_BUF;
        const uint32_t vb = sV + buf * FKV_BUF;
        #pragma unroll
        for (int t = 0; t < 8; t++) {
            int idx = tid + t * 256;
            int row = idx >> 5, c = idx & 31;
            cp16(kb + row * FKSTB + c * 16, Kt + (size_t)row * HD + c * 8);
        }
        CP_COMMIT();
        #pragma unroll
        for (int t = 0; t < 8; t++) {
            int idx = tid + t * 256;
            int row = idx >> 5, c = idx & 31;
            cp16(vb + row * FKSTB + c * 16, Vt + (size_t)row * HD + c * 8);
        }
        CP_COMMIT();
    };

    float accO[32][4];
    #pragma unroll
    for (int nj = 0; nj < 32; nj++)
        #pragma unroll
        for (int k = 0; k < 4; k++) accO[nj][k] = 0.f;
    float rm0 = -1e30f, rm1 = -1e30f, rl0 = 0.f, rl1 = 0.f;

    const uint32_t lrow = (lane & 15), lhi = (lane & 16);
    const float SC = 0.0625f * 1.44269504f;   // 1/sqrt(256) * log2(e)

    load_kv(0, 0);

    for (int kt = 0; kt < 32; kt++) {
        const int cur = kt & 1;
        if (kt < 31) { load_kv(kt + 1, cur ^ 1); CP_WAIT(2); }
        else         { CP_WAIT(0); }
        __syncthreads();
        const uint32_t sKb = sK + cur * FKV_BUF;
        const uint32_t sVb = sV + cur * FKV_BUF;

        // ---- S = Q K^T  (warp tile 16 x 64, k = 256) ----
        float accS[8][4];
        #pragma unroll
        for (int nj = 0; nj < 8; nj++)
            #pragma unroll
            for (int k = 0; k < 4; k++) accS[nj][k] = 0.f;
        #pragma unroll
        for (int ks = 0; ks < 16; ks++) {
            const uint32_t colb = ks * 32 + lhi;
            uint32_t a[4];
            ldmx4(sQ + (m0w + lrow) * FKSTB + colb, a[0], a[1], a[2], a[3]);
            #pragma unroll
            for (int kb = 0; kb < 4; kb++) {
                uint32_t br[4];
                ldmx4(sKb + (kb * 16 + lrow) * FKSTB + colb,
                      br[0], br[1], br[2], br[3]);
                mma16816(accS[kb * 2 + 0], a, br[0], br[2]);
                mma16816(accS[kb * 2 + 1], a, br[1], br[3]);
            }
        }

        // ---- register softmax (rows g and g+8 of this warp's 16) ----
        #pragma unroll
        for (int nj = 0; nj < 8; nj++)
            #pragma unroll
            for (int k = 0; k < 4; k++) accS[nj][k] *= SC;
        float mx0 = rm0, mx1 = rm1;
        #pragma unroll
        for (int nj = 0; nj < 8; nj++) {
            mx0 = fmaxf(mx0, fmaxf(accS[nj][0], accS[nj][1]));
            mx1 = fmaxf(mx1, fmaxf(accS[nj][2], accS[nj][3]));
        }
        mx0 = fmaxf(mx0, __shfl_xor_sync(0xffffffffu, mx0, 1));
        mx0 = fmaxf(mx0, __shfl_xor_sync(0xffffffffu, mx0, 2));
        mx1 = fmaxf(mx1, __shfl_xor_sync(0xffffffffu, mx1, 1));
        mx1 = fmaxf(mx1, __shfl_xor_sync(0xffffffffu, mx1, 2));
        const float al0 = ex2f(rm0 - mx0);
        const float al1 = ex2f(rm1 - mx1);
        rm0 = mx0; rm1 = mx1;

        float sum0 = 0.f, sum1 = 0.f;
        uint32_t pa[4][4];
        #pragma unroll
        for (int nj = 0; nj < 8; nj++) {
            float p0 = ex2f(accS[nj][0] - mx0);
            float p1 = ex2f(accS[nj][1] - mx0);
            float p2 = ex2f(accS[nj][2] - mx1);
            float p3 = ex2f(accS[nj][3] - mx1);
            sum0 += p0 + p1;
            sum1 += p2 + p3;
            __nv_bfloat162 h01 = __floats2bfloat162_rn(p0, p1);
            __nv_bfloat162 h23 = __floats2bfloat162_rn(p2, p3);
            const int kk = nj >> 1, hf = nj & 1;
            pa[kk][hf * 2 + 0] = *(uint32_t*)&h01;
            pa[kk][hf * 2 + 1] = *(uint32_t*)&h23;
        }
        sum0 += __shfl_xor_sync(0xffffffffu, sum0, 1);
        sum0 += __shfl_xor_sync(0xffffffffu, sum0, 2);
        sum1 += __shfl_xor_sync(0xffffffffu, sum1, 1);
        sum1 += __shfl_xor_sync(0xffffffffu, sum1, 2);
        rl0 = rl0 * al0 + sum0;
        rl1 = rl1 * al1 + sum1;

        // ---- O = O*alpha + P V  (warp tile 16 x 256, k = 64) ----
        #pragma unroll
        for (int nj = 0; nj < 32; nj++) {
            accO[nj][0] *= al0; accO[nj][1] *= al0;
            accO[nj][2] *= al1; accO[nj][3] *= al1;
        }
        #pragma unroll
        for (int ks = 0; ks < 4; ks++) {
            const uint32_t vrow = ks * 16 + lrow;
            #pragma unroll
            for (int np = 0; np < 16; np++) {
                uint32_t vb[4];
                ldmx4t(sVb + vrow * FKSTB + np * 32 + lhi,
                       vb[0], vb[1], vb[2], vb[3]);
                mma16816(accO[np * 2 + 0], pa[ks], vb[0], vb[1]);
                mma16816(accO[np * 2 + 1], pa[ks], vb[2], vb[3]);
            }
        }
        __syncthreads();
    }

    // ---- epilogue: O /= l, write bf16 to g_ao_bf [B,L,H*hd] ----
    const int b = bh >> 2, h = bh & 3;
    const int r0 = q0 + m0w + g;
    const float li0 = 1.0f / rl0;
    const float li1 = 1.0f / rl1;
    __nv_bfloat16* d1 = g_ao_bf + ((size_t)(b * LL + r0) * DD + h * HD);
    __nv_bfloat16* d2 = d1 + 8 * DD;
    #pragma unroll
    for (int nj = 0; nj < 32; nj++) {
        const int col = nj * 8 + qd * 2;
        __nv_bfloat162 h1 = __floats2bfloat162_rn(accO[nj][0] * li0,
                                                  accO[nj][1] * li0);
        __nv_bfloat162 h2 = __floats2bfloat162_rn(accO[nj][2] * li1,
                                                  accO[nj][3] * li1);
        *(uint32_t*)(d1 + col) = *(uint32_t*)&h1;
        *(uint32_t*)(d2 + col) = *(uint32_t*)&h2;
    }
}

// ---------------- launch -----------------------------------------------------
extern "C" void kernel_launch(void* const* d_in, const int* in_sizes, int n_in,
                              void* d_out, int out_size)
{
    const float* x      = (const float*)d_in[0];
    const float* norm_w = (const float*)d_in[1];
    const float* qkv_w  = (const float*)d_in[2];
    const float* out_w  = (const float*)d_in[3];
    const float* rsp    = (const float*)d_in[4];
    float* out = (float*)d_out;

    __nv_bfloat16 *p_xn, *p_wqkv, *p_wout, *p_ao, *p_qkv;
    cudaGetSymbolAddress((void**)&p_xn,   g_xn_bf);
    cudaGetSymbolAddress((void**)&p_wqkv, g_wqkv_bf);
    cudaGetSymbolAddress((void**)&p_wout, g_wout_bf);
    cudaGetSymbolAddress((void**)&p_qkv,  g_qkv_bf);
    cudaGetSymbolAddress((void**)&p_ao,   g_ao_bf);

    cudaFuncSetAttribute(flash_mma,
                         cudaFuncAttributeMaxDynamicSharedMemorySize,
                         FLASH_SMEM);
    cudaFuncSetAttribute(gemm_mma<false, true>,
                         cudaFuncAttributeMaxDynamicSharedMemorySize, GSMEM);
    cudaFuncSetAttribute(gemm_mma<true, false>,
                         cudaFuncAttributeMaxDynamicSharedMemorySize, GSMEM);

    // 0. weights -> bf16
    f2bf_kernel<<<(3 * DD * DD / 4 + 255) / 256, 256>>>(qkv_w, p_wqkv, 3 * DD * DD / 4);
    f2bf_kernel<<<(DD * DD / 4 + 255) / 256, 256>>>(out_w, p_wout, DD * DD / 4);
    // 1. RMSNorm (bf16 out)
    rmsnorm_kernel<<<ROWS, 256>>>(x, norm_w);
    // 2. QKV projection (mma.sync bf16, bf16 out): [8192,3072] = xn @ qkv_w^T
    gemm_mma<false, true><<<dim3((3 * DD) / 128, ROWS / 128), 128, GSMEM>>>(
        p_xn, p_wqkv, p_qkv, 3 * DD, DD, nullptr, nullptr);
    // 3. RoPE + scatter to bf16 [B,H,L,hd]
    rope_scatter_kernel<<<(ROWS * 1536) / 256, 256>>>();
    // 4. attention (register-resident FA2, bf16 mma.sync)
    flash_mma<<<dim3(LL / 128, BHN), 256, FLASH_SMEM>>>();
    // 5. out projection + residual epilogue -> d_out (fp32)
    gemm_mma<true, false><<<dim3(DD / 128, ROWS / 128), 128, GSMEM>>>(
        p_ao, p_wout, out, DD, DD, x, rsp);
}